// round 2
// baseline (speedup 1.0000x reference)
#include <cuda_runtime.h>
#include <math.h>

// Problem shape (fixed by the dataset)
#define BATCH 16
#define SEQ   4096
#define HID   1024

// Scratch (no cudaMalloc allowed)
__device__ float g_u[HID];
__device__ float g_energies[BATCH * SEQ];

// ---------------------------------------------------------------------------
// Kernel 1: u[h] = sum_k v[k] * W[k, HID + h]
// W is row-major (HID, 2*HID). Warp-coalesced over h.
// ---------------------------------------------------------------------------
__global__ void compute_u_kernel(const float* __restrict__ W,
                                 const float* __restrict__ v) {
    int h = blockIdx.x * blockDim.x + threadIdx.x;  // 0..HID-1
    if (h >= HID) return;
    float acc = 0.0f;
    const float* Wcol = W + (size_t)HID + h;  // W[0, HID+h]
#pragma unroll 4
    for (int k = 0; k < HID; k++) {
        acc = fmaf(__ldg(v + k), __ldg(Wcol + (size_t)k * (2 * HID)), acc);
    }
    g_u[h] = acc;
}

// ---------------------------------------------------------------------------
// Kernel 2: energies[b,s] = dot(enc[b,s,:], u)   — the 256MB streaming pass.
// One warp per (b,s) row. u cached in shared memory.
// ---------------------------------------------------------------------------
__global__ __launch_bounds__(256) void energies_kernel(
    const float* __restrict__ enc) {
    __shared__ float su[HID];
    for (int i = threadIdx.x; i < HID; i += blockDim.x) su[i] = g_u[i];
    __syncthreads();

    int gwarp = (blockIdx.x * blockDim.x + threadIdx.x) >> 5;  // row id
    int lane = threadIdx.x & 31;
    if (gwarp >= BATCH * SEQ) return;

    const float4* row = reinterpret_cast<const float4*>(enc + (size_t)gwarp * HID);
    const float4* uu = reinterpret_cast<const float4*>(su);

    float acc = 0.0f;
#pragma unroll
    for (int i = 0; i < HID / (32 * 4); i++) {  // 8 iterations
        float4 x = row[lane + i * 32];
        float4 u4 = uu[lane + i * 32];
        acc = fmaf(x.x, u4.x, acc);
        acc = fmaf(x.y, u4.y, acc);
        acc = fmaf(x.z, u4.z, acc);
        acc = fmaf(x.w, u4.w, acc);
    }
#pragma unroll
    for (int o = 16; o > 0; o >>= 1) acc += __shfl_xor_sync(0xFFFFFFFFu, acc, o);
    if (lane == 0) g_energies[gwarp] = acc;
}

// ---------------------------------------------------------------------------
// Kernel 3: per-batch softmax over SEQ. One block per batch.
// ---------------------------------------------------------------------------
__global__ __launch_bounds__(512) void softmax_kernel(float* __restrict__ out) {
    __shared__ float red[32];
    const float* e = g_energies + (size_t)blockIdx.x * SEQ;
    float* o = out + (size_t)blockIdx.x * SEQ;
    int tid = threadIdx.x;
    int lane = tid & 31;
    int warp = tid >> 5;
    int nwarps = blockDim.x >> 5;

    // --- max reduction ---
    float m = -INFINITY;
    for (int s = tid; s < SEQ; s += blockDim.x) m = fmaxf(m, e[s]);
#pragma unroll
    for (int of = 16; of > 0; of >>= 1) m = fmaxf(m, __shfl_xor_sync(~0u, m, of));
    if (lane == 0) red[warp] = m;
    __syncthreads();
    if (warp == 0) {
        float t = (lane < nwarps) ? red[lane] : -INFINITY;
#pragma unroll
        for (int of = 16; of > 0; of >>= 1) t = fmaxf(t, __shfl_xor_sync(~0u, t, of));
        if (lane == 0) red[0] = t;
    }
    __syncthreads();
    m = red[0];
    __syncthreads();

    // --- exp + sum ---
    float sum = 0.0f;
    for (int s = tid; s < SEQ; s += blockDim.x) {
        float t = __expf(e[s] - m);
        o[s] = t;
        sum += t;
    }
#pragma unroll
    for (int of = 16; of > 0; of >>= 1) sum += __shfl_xor_sync(~0u, sum, of);
    if (lane == 0) red[warp] = sum;
    __syncthreads();
    if (warp == 0) {
        float t = (lane < nwarps) ? red[lane] : 0.0f;
#pragma unroll
        for (int of = 16; of > 0; of >>= 1) t += __shfl_xor_sync(~0u, t, of);
        if (lane == 0) red[0] = t;
    }
    __syncthreads();
    float inv = 1.0f / red[0];

    // --- normalize ---
    for (int s = tid; s < SEQ; s += blockDim.x) o[s] *= inv;
}

// ---------------------------------------------------------------------------
// Launch. Input order: hidden, encoder_outputs, W, b, v.
// hidden and b are mathematically dead (softmax shift invariance).
// ---------------------------------------------------------------------------
extern "C" void kernel_launch(void* const* d_in, const int* in_sizes, int n_in,
                              void* d_out, int out_size) {
    const float* enc = (const float*)d_in[1];
    const float* W = (const float*)d_in[2];
    const float* v = (const float*)d_in[4];
    float* out = (float*)d_out;

    compute_u_kernel<<<HID / 128, 128>>>(W, v);

    // 65536 rows, 1 warp each, 8 warps/block -> 8192 blocks
    energies_kernel<<<(BATCH * SEQ) / 8, 256>>>(enc);

    softmax_kernel<<<BATCH, 512>>>(out);
}

// round 3
// speedup vs baseline: 3.4621x; 3.4621x over previous
#include <cuda_runtime.h>
#include <math.h>

// Problem shape (fixed by the dataset)
#define BATCH 16
#define SEQ   4096
#define HID   1024
#define KCHUNKS 16
#define KPER   (HID / KCHUNKS)   // 64

// Scratch (no cudaMalloc allowed)
__device__ float g_u_part[KCHUNKS][HID];
__device__ float g_u[HID];
__device__ float g_energies[BATCH * SEQ];

// ---------------------------------------------------------------------------
// Kernel 1a: partial u over a k-chunk.
// grid = (HID/128, KCHUNKS), block = 128.
// u_part[c][h] = sum_{k in chunk c} v[k] * W[k, HID + h]
// ---------------------------------------------------------------------------
__global__ __launch_bounds__(128) void compute_u_part_kernel(
    const float* __restrict__ W, const float* __restrict__ v) {
    int h = blockIdx.x * 128 + threadIdx.x;
    int c = blockIdx.y;
    int k0 = c * KPER;
    const float* Wp = W + (size_t)k0 * (2 * HID) + HID + h;
    float acc = 0.0f;
#pragma unroll 8
    for (int k = 0; k < KPER; k++) {
        acc = fmaf(__ldg(v + k0 + k), __ldg(Wp + (size_t)k * (2 * HID)), acc);
    }
    g_u_part[c][h] = acc;
}

// ---------------------------------------------------------------------------
// Kernel 1b: reduce partials. One block of 1024 threads.
// ---------------------------------------------------------------------------
__global__ __launch_bounds__(1024) void reduce_u_kernel() {
    int h = threadIdx.x;
    float acc = 0.0f;
#pragma unroll
    for (int c = 0; c < KCHUNKS; c++) acc += g_u_part[c][h];
    g_u[h] = acc;
}

// ---------------------------------------------------------------------------
// Kernel 2: energies[b,s] = dot(enc[b,s,:], u)   — the 256MB streaming pass.
// One warp per (b,s) row. u cached in shared memory.
// ---------------------------------------------------------------------------
__global__ __launch_bounds__(256) void energies_kernel(
    const float* __restrict__ enc) {
    __shared__ float su[HID];
    for (int i = threadIdx.x; i < HID; i += blockDim.x) su[i] = g_u[i];
    __syncthreads();

    int gwarp = (blockIdx.x * blockDim.x + threadIdx.x) >> 5;  // row id
    int lane = threadIdx.x & 31;
    if (gwarp >= BATCH * SEQ) return;

    const float4* row = reinterpret_cast<const float4*>(enc + (size_t)gwarp * HID);
    const float4* uu = reinterpret_cast<const float4*>(su);

    float acc = 0.0f;
#pragma unroll
    for (int i = 0; i < HID / (32 * 4); i++) {  // 8 iterations
        float4 x = row[lane + i * 32];
        float4 u4 = uu[lane + i * 32];
        acc = fmaf(x.x, u4.x, acc);
        acc = fmaf(x.y, u4.y, acc);
        acc = fmaf(x.z, u4.z, acc);
        acc = fmaf(x.w, u4.w, acc);
    }
#pragma unroll
    for (int o = 16; o > 0; o >>= 1) acc += __shfl_xor_sync(0xFFFFFFFFu, acc, o);
    if (lane == 0) g_energies[gwarp] = acc;
}

// ---------------------------------------------------------------------------
// Kernel 3: per-batch softmax over SEQ. One block per batch.
// ---------------------------------------------------------------------------
__global__ __launch_bounds__(512) void softmax_kernel(float* __restrict__ out) {
    __shared__ float red[32];
    const float* e = g_energies + (size_t)blockIdx.x * SEQ;
    float* o = out + (size_t)blockIdx.x * SEQ;
    int tid = threadIdx.x;
    int lane = tid & 31;
    int warp = tid >> 5;
    int nwarps = blockDim.x >> 5;

    // --- max reduction ---
    float m = -INFINITY;
    for (int s = tid; s < SEQ; s += blockDim.x) m = fmaxf(m, e[s]);
#pragma unroll
    for (int of = 16; of > 0; of >>= 1) m = fmaxf(m, __shfl_xor_sync(~0u, m, of));
    if (lane == 0) red[warp] = m;
    __syncthreads();
    if (warp == 0) {
        float t = (lane < nwarps) ? red[lane] : -INFINITY;
#pragma unroll
        for (int of = 16; of > 0; of >>= 1) t = fmaxf(t, __shfl_xor_sync(~0u, t, of));
        if (lane == 0) red[0] = t;
    }
    __syncthreads();
    m = red[0];
    __syncthreads();

    // --- exp + sum ---
    float sum = 0.0f;
    for (int s = tid; s < SEQ; s += blockDim.x) {
        float t = __expf(e[s] - m);
        o[s] = t;
        sum += t;
    }
#pragma unroll
    for (int of = 16; of > 0; of >>= 1) sum += __shfl_xor_sync(~0u, sum, of);
    if (lane == 0) red[warp] = sum;
    __syncthreads();
    if (warp == 0) {
        float t = (lane < nwarps) ? red[lane] : 0.0f;
#pragma unroll
        for (int of = 16; of > 0; of >>= 1) t += __shfl_xor_sync(~0u, t, of);
        if (lane == 0) red[0] = t;
    }
    __syncthreads();
    float inv = 1.0f / red[0];

    // --- normalize ---
    for (int s = tid; s < SEQ; s += blockDim.x) o[s] *= inv;
}

// ---------------------------------------------------------------------------
// Launch. Input order: hidden, encoder_outputs, W, b, v.
// hidden and b are mathematically dead (softmax shift invariance).
// ---------------------------------------------------------------------------
extern "C" void kernel_launch(void* const* d_in, const int* in_sizes, int n_in,
                              void* d_out, int out_size) {
    const float* enc = (const float*)d_in[1];
    const float* W = (const float*)d_in[2];
    const float* v = (const float*)d_in[4];
    float* out = (float*)d_out;

    compute_u_part_kernel<<<dim3(HID / 128, KCHUNKS), 128>>>(W, v);
    reduce_u_kernel<<<1, HID>>>();

    // 65536 rows, 1 warp each, 8 warps/block -> 8192 blocks
    energies_kernel<<<(BATCH * SEQ) / 8, 256>>>(enc);

    softmax_kernel<<<BATCH, 512>>>(out);
}

// round 4
// speedup vs baseline: 3.8570x; 1.1140x over previous
#include <cuda_runtime.h>
#include <math.h>

// Problem shape (fixed by the dataset)
#define BATCH 16
#define SEQ   4096
#define HID   1024
#define KCHUNKS 16
#define KPER   (HID / KCHUNKS)   // 64

// Scratch (no cudaMalloc allowed)
__device__ float g_u_part[KCHUNKS][HID];
__device__ float g_u[HID];
__device__ float g_energies[BATCH * SEQ];

// ---------------------------------------------------------------------------
// Kernel 1a: partial u over a k-chunk.
// grid = (HID/128, KCHUNKS), block = 128.
// ---------------------------------------------------------------------------
__global__ __launch_bounds__(128) void compute_u_part_kernel(
    const float* __restrict__ W, const float* __restrict__ v) {
    int h = blockIdx.x * 128 + threadIdx.x;
    int c = blockIdx.y;
    int k0 = c * KPER;
    const float* Wp = W + (size_t)k0 * (2 * HID) + HID + h;
    float acc = 0.0f;
#pragma unroll 8
    for (int k = 0; k < KPER; k++) {
        acc = fmaf(__ldg(v + k0 + k), __ldg(Wp + (size_t)k * (2 * HID)), acc);
    }
    g_u_part[c][h] = acc;
}

// ---------------------------------------------------------------------------
// Kernel 1b: reduce partials. One block of 1024 threads.
// ---------------------------------------------------------------------------
__global__ __launch_bounds__(1024) void reduce_u_kernel() {
    int h = threadIdx.x;
    float acc = 0.0f;
#pragma unroll
    for (int c = 0; c < KCHUNKS; c++) acc += g_u_part[c][h];
    g_u[h] = acc;
}

// ---------------------------------------------------------------------------
// Kernel 2: energies[b,s] = dot(enc[b,s,:], u)   — the 256MB streaming pass.
// One warp per (b,s) row; u in shared; __ldcs (evict-first) on the stream.
// ---------------------------------------------------------------------------
__global__ __launch_bounds__(256) void energies_kernel(
    const float* __restrict__ enc) {
    __shared__ float su[HID];
    for (int i = threadIdx.x; i < HID; i += blockDim.x) su[i] = g_u[i];
    __syncthreads();

    int gwarp = (blockIdx.x * blockDim.x + threadIdx.x) >> 5;  // row id
    int lane = threadIdx.x & 31;
    if (gwarp >= BATCH * SEQ) return;

    const float4* row = reinterpret_cast<const float4*>(enc + (size_t)gwarp * HID);
    const float4* uu = reinterpret_cast<const float4*>(su);

    float acc = 0.0f;
#pragma unroll
    for (int i = 0; i < HID / (32 * 4); i++) {  // 8 iterations
        float4 x = __ldcs(row + lane + i * 32);
        float4 u4 = uu[lane + i * 32];
        acc = fmaf(x.x, u4.x, acc);
        acc = fmaf(x.y, u4.y, acc);
        acc = fmaf(x.z, u4.z, acc);
        acc = fmaf(x.w, u4.w, acc);
    }
#pragma unroll
    for (int o = 16; o > 0; o >>= 1) acc += __shfl_xor_sync(0xFFFFFFFFu, acc, o);
    if (lane == 0) g_energies[gwarp] = acc;
}

// ---------------------------------------------------------------------------
// Kernel 3: per-batch softmax. 1024 threads/block, one float4 per thread.
// Single global read + single global write; reductions register/smem-resident.
// ---------------------------------------------------------------------------
__global__ __launch_bounds__(1024) void softmax_kernel(float* __restrict__ out) {
    __shared__ float red[32];
    int tid = threadIdx.x;
    int lane = tid & 31;
    int warp = tid >> 5;

    const float4* e4 = reinterpret_cast<const float4*>(g_energies + (size_t)blockIdx.x * SEQ);
    float4* o4 = reinterpret_cast<float4*>(out + (size_t)blockIdx.x * SEQ);

    float4 x = e4[tid];

    // --- max ---
    float m = fmaxf(fmaxf(x.x, x.y), fmaxf(x.z, x.w));
#pragma unroll
    for (int of = 16; of > 0; of >>= 1) m = fmaxf(m, __shfl_xor_sync(~0u, m, of));
    if (lane == 0) red[warp] = m;
    __syncthreads();
    {
        float t = red[lane];  // 32 warps -> all lanes valid
#pragma unroll
        for (int of = 16; of > 0; of >>= 1) t = fmaxf(t, __shfl_xor_sync(~0u, t, of));
        m = t;
    }

    // --- exp + sum ---
    x.x = __expf(x.x - m);
    x.y = __expf(x.y - m);
    x.z = __expf(x.z - m);
    x.w = __expf(x.w - m);
    float sum = x.x + x.y + x.z + x.w;
#pragma unroll
    for (int of = 16; of > 0; of >>= 1) sum += __shfl_xor_sync(~0u, sum, of);
    __syncthreads();  // red reuse
    if (lane == 0) red[warp] = sum;
    __syncthreads();
    {
        float t = red[lane];
#pragma unroll
        for (int of = 16; of > 0; of >>= 1) t += __shfl_xor_sync(~0u, t, of);
        sum = t;
    }

    float inv = __frcp_rn(sum);
    x.x *= inv; x.y *= inv; x.z *= inv; x.w *= inv;
    o4[tid] = x;
}

// ---------------------------------------------------------------------------
// Launch. Input order: hidden, encoder_outputs, W, b, v.
// hidden and b are mathematically dead (softmax shift invariance).
// ---------------------------------------------------------------------------
extern "C" void kernel_launch(void* const* d_in, const int* in_sizes, int n_in,
                              void* d_out, int out_size) {
    const float* enc = (const float*)d_in[1];
    const float* W = (const float*)d_in[2];
    const float* v = (const float*)d_in[4];
    float* out = (float*)d_out;

    compute_u_part_kernel<<<dim3(HID / 128, KCHUNKS), 128>>>(W, v);
    reduce_u_kernel<<<1, HID>>>();

    // 65536 rows, 1 warp each, 8 warps/block -> 8192 blocks
    energies_kernel<<<(BATCH * SEQ) / 8, 256>>>(enc);

    softmax_kernel<<<BATCH, 1024>>>(out);
}